// round 1
// baseline (speedup 1.0000x reference)
#include <cuda_runtime.h>
#include <cstdint>

#define TT 512
#define BB 256
#define HH 64
#define GG 256     // 4*H
#define RROWS 2    // batch rows per recurrence CTA -> 128 CTAs

// Scratch (device globals; no allocation in kernel_launch)
__device__ float g_gx[(size_t)TT * BB * GG];   // [T][B][4H]  128 MiB
__device__ float g_hA[(size_t)TT * BB * HH];   // [T][B][H]   32 MiB
__device__ float g_hB[(size_t)TT * BB * HH];

__device__ __forceinline__ float sigf(float x)   { return 1.0f / (1.0f + __expf(-x)); }
__device__ __forceinline__ float tanhfast(float x){ return 2.0f / (1.0f + __expf(-2.0f * x)) - 1.0f; }

// ---------------------------------------------------------------------------
// Layer 0 input projection: d_in = 2.
// gx[t][b][g] = x[b][t][0]*Wih[g][0] + x[b][t][1]*Wih[g][1] + bih[g] + bhh[g]
// grid = T, block = 256 (one thread per gate index)
// ---------------------------------------------------------------------------
__global__ __launch_bounds__(256) void lstm_gx0_kernel(
    const float* __restrict__ x,      // [B][T][2]
    const float* __restrict__ Wih,    // [256][2]
    const float* __restrict__ bih,
    const float* __restrict__ bhh,
    float* __restrict__ gxout)        // [T][B][256]
{
    __shared__ float xs[2 * BB];
    const int t = blockIdx.x;
    const int tid = threadIdx.x;

    xs[2 * tid]     = x[((size_t)tid * TT + t) * 2 + 0];
    xs[2 * tid + 1] = x[((size_t)tid * TT + t) * 2 + 1];
    const float w0   = Wih[tid * 2];
    const float w1   = Wih[tid * 2 + 1];
    const float bias = bih[tid] + bhh[tid];
    __syncthreads();

    float* op = gxout + (size_t)t * BB * GG + tid;
#pragma unroll 4
    for (int r = 0; r < BB; r++) {
        op[r * GG] = fmaf(xs[2 * r], w0, fmaf(xs[2 * r + 1], w1, bias));
    }
}

// ---------------------------------------------------------------------------
// Layers 1..4 input projection: GEMM [T*B, 64] x [64, 256] + bias.
// W row per thread in registers; x tile broadcast from smem (conflict-free).
// grid = T*B/64, block = 256.
// ---------------------------------------------------------------------------
__global__ __launch_bounds__(256, 2) void lstm_gx_kernel(
    const float* __restrict__ xseq,   // [T][B][64]
    const float* __restrict__ Wih,    // [256][64]
    const float* __restrict__ bih,
    const float* __restrict__ bhh,
    float* __restrict__ gxout)        // [T][B][256]
{
    __shared__ float4 xs4[64 * 16];   // 64 rows x 64 floats
    const int tid = threadIdx.x;
    const size_t base = (size_t)blockIdx.x * 64;

    const float4* xin = reinterpret_cast<const float4*>(xseq + base * HH);
    for (int i = tid; i < 64 * 16; i += 256) xs4[i] = xin[i];

    float4 w4[16];
    const float4* wp = reinterpret_cast<const float4*>(Wih + tid * HH);
#pragma unroll
    for (int i = 0; i < 16; i++) w4[i] = wp[i];
    const float bias = bih[tid] + bhh[tid];
    __syncthreads();

    float* op = gxout + base * GG + tid;
#pragma unroll 1
    for (int r0 = 0; r0 < 64; r0 += 4) {
        float a0 = bias, a1 = bias, a2 = bias, a3 = bias;
#pragma unroll
        for (int k4 = 0; k4 < 16; k4++) {
            const float4 wv = w4[k4];
            float4 xv;
            xv = xs4[(r0 + 0) * 16 + k4];
            a0 = fmaf(wv.x, xv.x, a0); a0 = fmaf(wv.y, xv.y, a0);
            a0 = fmaf(wv.z, xv.z, a0); a0 = fmaf(wv.w, xv.w, a0);
            xv = xs4[(r0 + 1) * 16 + k4];
            a1 = fmaf(wv.x, xv.x, a1); a1 = fmaf(wv.y, xv.y, a1);
            a1 = fmaf(wv.z, xv.z, a1); a1 = fmaf(wv.w, xv.w, a1);
            xv = xs4[(r0 + 2) * 16 + k4];
            a2 = fmaf(wv.x, xv.x, a2); a2 = fmaf(wv.y, xv.y, a2);
            a2 = fmaf(wv.z, xv.z, a2); a2 = fmaf(wv.w, xv.w, a2);
            xv = xs4[(r0 + 3) * 16 + k4];
            a3 = fmaf(wv.x, xv.x, a3); a3 = fmaf(wv.y, xv.y, a3);
            a3 = fmaf(wv.z, xv.z, a3); a3 = fmaf(wv.w, xv.w, a3);
        }
        op[(r0 + 0) * GG] = a0;
        op[(r0 + 1) * GG] = a1;
        op[(r0 + 2) * GG] = a2;
        op[(r0 + 3) * GG] = a3;
    }
}

// ---------------------------------------------------------------------------
// Recurrence: one CTA handles RROWS=2 batch rows for all 512 steps.
// Thread tid = gate index (0..255). W_hh row in registers, h broadcast from
// smem. gx for t+1 prefetched into registers during step t's compute.
// grid = B/RROWS = 128, block = 256.
// ---------------------------------------------------------------------------
__global__ __launch_bounds__(256, 1) void lstm_rec_kernel(
    const float* __restrict__ gx,     // [T][B][256]
    const float* __restrict__ Whh,    // [256][64]
    float* __restrict__ hout)         // [T][B][64]
{
    __shared__ float h_s[RROWS * HH];
    __shared__ float gatebuf[RROWS * GG];
    const int tid = threadIdx.x;
    const int row0 = blockIdx.x * RROWS;

    float4 w4[16];
    {
        const float4* wp = reinterpret_cast<const float4*>(Whh + tid * HH);
#pragma unroll
        for (int i = 0; i < 16; i++) w4[i] = wp[i];
    }

    float c = 0.0f;                       // cell state for update threads (tid < 128)
    if (tid < RROWS * HH) h_s[tid] = 0.0f;
    __syncthreads();

    float gx0 = gx[((size_t)0 * BB + row0)     * GG + tid];
    float gx1 = gx[((size_t)0 * BB + row0 + 1) * GG + tid];

    for (int t = 0; t < TT; t++) {
        // prefetch next step's gx (consumed only after next barrier)
        float nx0 = 0.0f, nx1 = 0.0f;
        if (t + 1 < TT) {
            nx0 = __ldg(&gx[((size_t)(t + 1) * BB + row0)     * GG + tid]);
            nx1 = __ldg(&gx[((size_t)(t + 1) * BB + row0 + 1) * GG + tid]);
        }

        // gates = gx + h @ Whh^T  (two partial chains per row to halve latency)
        float a0 = gx0, b0 = 0.0f, a1 = gx1, b1 = 0.0f;
        const float4* h40 = reinterpret_cast<const float4*>(h_s);
        const float4* h41 = reinterpret_cast<const float4*>(h_s + HH);
#pragma unroll
        for (int k4 = 0; k4 < 16; k4 += 2) {
            float4 wv = w4[k4];
            float4 x0 = h40[k4];
            a0 = fmaf(wv.x, x0.x, a0); a0 = fmaf(wv.y, x0.y, a0);
            a0 = fmaf(wv.z, x0.z, a0); a0 = fmaf(wv.w, x0.w, a0);
            float4 x1 = h41[k4];
            a1 = fmaf(wv.x, x1.x, a1); a1 = fmaf(wv.y, x1.y, a1);
            a1 = fmaf(wv.z, x1.z, a1); a1 = fmaf(wv.w, x1.w, a1);
            float4 wu = w4[k4 + 1];
            float4 y0 = h40[k4 + 1];
            b0 = fmaf(wu.x, y0.x, b0); b0 = fmaf(wu.y, y0.y, b0);
            b0 = fmaf(wu.z, y0.z, b0); b0 = fmaf(wu.w, y0.w, b0);
            float4 y1 = h41[k4 + 1];
            b1 = fmaf(wu.x, y1.x, b1); b1 = fmaf(wu.y, y1.y, b1);
            b1 = fmaf(wu.z, y1.z, b1); b1 = fmaf(wu.w, y1.w, b1);
        }
        gatebuf[tid]      = a0 + b0;
        gatebuf[GG + tid] = a1 + b1;
        __syncthreads();

        // cell update: thread u < 128 owns (r = u/64, j = u%64)
        if (tid < RROWS * HH) {
            const int r = tid >> 6;
            const int j = tid & 63;
            const float* gb = gatebuf + r * GG;
            const float ig = sigf(gb[j]);
            const float fg = sigf(gb[64 + j]);
            const float gv = tanhfast(gb[128 + j]);
            const float og = sigf(gb[192 + j]);
            c = fmaf(fg, c, ig * gv);
            const float h = og * tanhfast(c);
            h_s[tid] = h;
            hout[((size_t)t * BB + row0 + r) * HH + j] = h;
        }
        __syncthreads();
        gx0 = nx0;
        gx1 = nx1;
    }
}

// ---------------------------------------------------------------------------
// Final linear head: out[b][t] = hseq[t][b][:] . Wl + bl
// grid = T, block = 256 (one thread per batch element)
// ---------------------------------------------------------------------------
__global__ __launch_bounds__(256) void lstm_lin_kernel(
    const float* __restrict__ hseq,   // [T][B][64]
    const float* __restrict__ Wl,     // [64]
    const float* __restrict__ bl,     // [1]
    float* __restrict__ out)          // [B][T]
{
    __shared__ float4 wl4[16];
    const int t = blockIdx.x;
    const int b = threadIdx.x;
    if (threadIdx.x < 16)
        wl4[threadIdx.x] = reinterpret_cast<const float4*>(Wl)[threadIdx.x];
    __syncthreads();

    const float4* hp = reinterpret_cast<const float4*>(hseq + ((size_t)t * BB + b) * HH);
    float acc = bl[0];
#pragma unroll
    for (int k4 = 0; k4 < 16; k4++) {
        const float4 h = hp[k4];
        const float4 w = wl4[k4];
        acc = fmaf(h.x, w.x, acc);
        acc = fmaf(h.y, w.y, acc);
        acc = fmaf(h.z, w.z, acc);
        acc = fmaf(h.w, w.w, acc);
    }
    out[(size_t)b * TT + t] = acc;
}

// ---------------------------------------------------------------------------
extern "C" void kernel_launch(void* const* d_in, const int* in_sizes, int n_in,
                              void* d_out, int out_size)
{
    (void)in_sizes; (void)n_in; (void)out_size;

    const float* x = (const float*)d_in[0];
    const float* Wih[5]; const float* Whh[5]; const float* bih[5]; const float* bhh[5];
    for (int l = 0; l < 5; l++) {
        Wih[l] = (const float*)d_in[1 + 4 * l];
        Whh[l] = (const float*)d_in[2 + 4 * l];
        bih[l] = (const float*)d_in[3 + 4 * l];
        bhh[l] = (const float*)d_in[4 + 4 * l];
    }
    const float* Wl = (const float*)d_in[21];
    const float* bl = (const float*)d_in[22];
    float* out = (float*)d_out;

    float *gx, *hA, *hB;
    cudaGetSymbolAddress((void**)&gx, g_gx);
    cudaGetSymbolAddress((void**)&hA, g_hA);
    cudaGetSymbolAddress((void**)&hB, g_hB);
    float* bufs[2] = { hA, hB };

    // layer 0
    lstm_gx0_kernel<<<TT, 256>>>(x, Wih[0], bih[0], bhh[0], gx);
    lstm_rec_kernel<<<BB / RROWS, 256>>>(gx, Whh[0], bufs[0]);

    // layers 1..4
    for (int l = 1; l < 5; l++) {
        const float* hin = bufs[(l - 1) & 1];
        float* ho = bufs[l & 1];
        lstm_gx_kernel<<<(TT * BB) / 64, 256>>>(hin, Wih[l], bih[l], bhh[l], gx);
        lstm_rec_kernel<<<BB / RROWS, 256>>>(gx, Whh[l], ho);
    }

    // linear head (layer 4 wrote bufs[0])
    lstm_lin_kernel<<<TT, 256>>>(bufs[0], Wl, bl, out);
}

// round 2
// speedup vs baseline: 1.1470x; 1.1470x over previous
#include <cuda_runtime.h>
#include <cstdint>

#define TT 512
#define BB 256
#define HH 64
#define GG 256     // 4*H
#define RROWS 2    // batch rows per recurrence CTA -> 128 CTAs

// Scratch (device globals; no allocation in kernel_launch)
__device__ float g_gx[(size_t)TT * BB * GG];   // [T][B][4H] permuted col order
__device__ float g_hA[(size_t)TT * BB * HH];   // [T][B][H]
__device__ float g_hB[(size_t)TT * BB * HH];

// ---- packed fp32x2 helpers (Blackwell FFMA2 via PTX) ----------------------
__device__ __forceinline__ unsigned long long ffma2(unsigned long long a,
                                                    unsigned long long b,
                                                    unsigned long long c) {
    unsigned long long d;
    asm("fma.rn.f32x2 %0, %1, %2, %3;" : "=l"(d) : "l"(a), "l"(b), "l"(c));
    return d;
}
__device__ __forceinline__ unsigned long long fadd2(unsigned long long a,
                                                    unsigned long long b) {
    unsigned long long d;
    asm("add.rn.f32x2 %0, %1, %2;" : "=l"(d) : "l"(a), "l"(b));
    return d;
}
__device__ __forceinline__ float2 unpack2(unsigned long long v) {
    float2 r;
    asm("mov.b64 {%0, %1}, %2;" : "=f"(r.x), "=f"(r.y) : "l"(v));
    return r;
}

// gate index permutation: thread tid <-> (j = tid>>2, g = tid&3), torch row = g*64+j
__device__ __forceinline__ int perm_row(int tid) { return (tid & 3) * 64 + (tid >> 2); }

// ---------------------------------------------------------------------------
// Layer 0 input projection (d_in = 2), writes permuted gx layout.
// grid = T, block = 256
// ---------------------------------------------------------------------------
__global__ __launch_bounds__(256) void lstm_gx0_kernel(
    const float* __restrict__ x,      // [B][T][2]
    const float* __restrict__ Wih,    // [256][2]
    const float* __restrict__ bih,
    const float* __restrict__ bhh,
    float* __restrict__ gxout)        // [T][B][256] permuted
{
    __shared__ float xs[2 * BB];
    const int t = blockIdx.x;
    const int tid = threadIdx.x;
    const int wr = perm_row(tid);

    xs[2 * tid]     = x[((size_t)tid * TT + t) * 2 + 0];
    xs[2 * tid + 1] = x[((size_t)tid * TT + t) * 2 + 1];
    const float w0   = Wih[wr * 2];
    const float w1   = Wih[wr * 2 + 1];
    const float bias = bih[wr] + bhh[wr];
    __syncthreads();

    float* op = gxout + (size_t)t * BB * GG + tid;
#pragma unroll 4
    for (int r = 0; r < BB; r++) {
        op[r * GG] = fmaf(xs[2 * r], w0, fmaf(xs[2 * r + 1], w1, bias));
    }
}

// ---------------------------------------------------------------------------
// Layers 1..4 input projection: [T*B,64] x [64,256] + bias, FFMA2 packed.
// Writes permuted gx layout. grid = T*B/64, block = 256.
// ---------------------------------------------------------------------------
__global__ __launch_bounds__(256, 2) void lstm_gx_kernel(
    const float* __restrict__ xseq,   // [T][B][64]
    const float* __restrict__ Wih,    // [256][64]
    const float* __restrict__ bih,
    const float* __restrict__ bhh,
    float* __restrict__ gxout)        // [T][B][256] permuted
{
    __shared__ float4 xs4[64 * 16];   // 64 rows x 64 floats
    const int tid = threadIdx.x;
    const size_t base = (size_t)blockIdx.x * 64;
    const int wr = perm_row(tid);

    const float4* xin = reinterpret_cast<const float4*>(xseq + base * HH);
    for (int i = tid; i < 64 * 16; i += 256) xs4[i] = xin[i];

    // W row as 32 packed f32x2
    unsigned long long w[32];
    {
        const double2* wp = reinterpret_cast<const double2*>(Wih + wr * HH);
#pragma unroll
        for (int i = 0; i < 16; i++) {
            double2 d = wp[i];
            w[2 * i]     = __double_as_longlong(d.x);
            w[2 * i + 1] = __double_as_longlong(d.y);
        }
    }
    const float bias = bih[wr] + bhh[wr];
    __syncthreads();

    const double2* xsd = reinterpret_cast<const double2*>(xs4);
    float* op = gxout + base * GG + tid;
#pragma unroll 1
    for (int r0 = 0; r0 < 64; r0 += 4) {
        unsigned long long a0 = 0ull, a1 = 0ull, a2 = 0ull, a3 = 0ull;
#pragma unroll
        for (int i = 0; i < 16; i++) {
            const unsigned long long wl = w[2 * i], wh = w[2 * i + 1];
            double2 xv;
            xv = xsd[(r0 + 0) * 16 + i];
            a0 = ffma2(wl, __double_as_longlong(xv.x), a0);
            a0 = ffma2(wh, __double_as_longlong(xv.y), a0);
            xv = xsd[(r0 + 1) * 16 + i];
            a1 = ffma2(wl, __double_as_longlong(xv.x), a1);
            a1 = ffma2(wh, __double_as_longlong(xv.y), a1);
            xv = xsd[(r0 + 2) * 16 + i];
            a2 = ffma2(wl, __double_as_longlong(xv.x), a2);
            a2 = ffma2(wh, __double_as_longlong(xv.y), a2);
            xv = xsd[(r0 + 3) * 16 + i];
            a3 = ffma2(wl, __double_as_longlong(xv.x), a3);
            a3 = ffma2(wh, __double_as_longlong(xv.y), a3);
        }
        float2 s0 = unpack2(a0), s1 = unpack2(a1), s2 = unpack2(a2), s3 = unpack2(a3);
        op[(r0 + 0) * GG] = bias + s0.x + s0.y;
        op[(r0 + 1) * GG] = bias + s1.x + s1.y;
        op[(r0 + 2) * GG] = bias + s2.x + s2.y;
        op[(r0 + 3) * GG] = bias + s3.x + s3.y;
    }
}

// ---------------------------------------------------------------------------
// Recurrence: quad-mapped threads, FFMA2 dot products, ONE barrier per step.
// thread tid -> (j = tid>>2, gate g = tid&3); computes that gate for both
// batch rows; quad shuffles gather the 4 activated gates; every lane keeps
// redundant (identical) c state. h double-buffered in smem.
// grid = 128, block = 256.
// ---------------------------------------------------------------------------
__global__ __launch_bounds__(256, 1) void lstm_rec_kernel(
    const float* __restrict__ gx,     // [T][B][256] permuted
    const float* __restrict__ Whh,    // [256][64]
    float* __restrict__ hout)         // [T][B][64]
{
    __shared__ float h_s[2][RROWS * HH];
    const int tid = threadIdx.x;
    const int j = tid >> 2, g = tid & 3;
    const int row0 = blockIdx.x * RROWS;
    const int wr = g * 64 + j;

    // W_hh row as 32 packed f32x2
    unsigned long long w[32];
    {
        const double2* wp = reinterpret_cast<const double2*>(Whh + wr * HH);
#pragma unroll
        for (int i = 0; i < 16; i++) {
            double2 d = wp[i];
            w[2 * i]     = __double_as_longlong(d.x);
            w[2 * i + 1] = __double_as_longlong(d.y);
        }
    }

    float c0 = 0.0f, c1 = 0.0f;
    if (tid < RROWS * HH) h_s[0][tid] = 0.0f;
    __syncthreads();

    float gx0 = gx[((size_t)0 * BB + row0)     * GG + tid];
    float gx1 = gx[((size_t)0 * BB + row0 + 1) * GG + tid];

    const float isG = (g == 2) ? 1.0f : 0.0f;   // tanh gate selector

    for (int t = 0; t < TT; t++) {
        const int p = t & 1;
        // prefetch next gx
        float nx0 = 0.0f, nx1 = 0.0f;
        if (t + 1 < TT) {
            nx0 = __ldg(&gx[((size_t)(t + 1) * BB + row0)     * GG + tid]);
            nx1 = __ldg(&gx[((size_t)(t + 1) * BB + row0 + 1) * GG + tid]);
        }

        // packed dot: gate(r) = gx(r) + W_row . h(r)
        unsigned long long a0 = 0ull, b0 = 0ull, a1 = 0ull, b1 = 0ull;
        const double2* h0p = reinterpret_cast<const double2*>(h_s[p]);
        const double2* h1p = reinterpret_cast<const double2*>(h_s[p] + HH);
#pragma unroll
        for (int i = 0; i < 16; i++) {
            const unsigned long long wl = w[2 * i], wh = w[2 * i + 1];
            double2 hv0 = h0p[i];
            a0 = ffma2(wl, __double_as_longlong(hv0.x), a0);
            b0 = ffma2(wh, __double_as_longlong(hv0.y), b0);
            double2 hv1 = h1p[i];
            a1 = ffma2(wl, __double_as_longlong(hv1.x), a1);
            b1 = ffma2(wh, __double_as_longlong(hv1.y), b1);
        }
        float2 s0 = unpack2(fadd2(a0, b0));
        float2 s1 = unpack2(fadd2(a1, b1));
        const float v0 = gx0 + s0.x + s0.y;
        const float v1 = gx1 + s1.x + s1.y;

        // branchless activation: sigmoid for g in {0,1,3}, tanh for g==2
        // tanh(x) = 2/(1+e^{-2x}) - 1 ; sig(x) = 1/(1+e^{-x})
        const float e0 = __expf(-(1.0f + isG) * v0);
        const float e1 = __expf(-(1.0f + isG) * v1);
        const float r0 = (1.0f + isG) / (1.0f + e0) - isG;
        const float r1 = (1.0f + isG) / (1.0f + e1) - isG;

        // quad gather (gates i,f,g,o live in lanes 0..3 of each quad)
        const unsigned m = 0xffffffffu;
        const float i0 = __shfl_sync(m, r0, 0, 4);
        const float f0 = __shfl_sync(m, r0, 1, 4);
        const float G0 = __shfl_sync(m, r0, 2, 4);
        const float o0 = __shfl_sync(m, r0, 3, 4);
        const float i1 = __shfl_sync(m, r1, 0, 4);
        const float f1 = __shfl_sync(m, r1, 1, 4);
        const float G1 = __shfl_sync(m, r1, 2, 4);
        const float o1 = __shfl_sync(m, r1, 3, 4);

        c0 = fmaf(f0, c0, i0 * G0);
        c1 = fmaf(f1, c1, i1 * G1);
        const float tc0 = 2.0f / (1.0f + __expf(-2.0f * c0)) - 1.0f;
        const float tc1 = 2.0f / (1.0f + __expf(-2.0f * c1)) - 1.0f;
        const float h0v = o0 * tc0;
        const float h1v = o1 * tc1;

        float* hn = h_s[p ^ 1];
        if (g < 2) hn[g * HH + j] = (g == 0) ? h0v : h1v;
        __syncthreads();   // the ONLY barrier per step

        // coalesced global store of this step's h
        if (tid < RROWS * HH)
            hout[((size_t)t * BB + row0 + (tid >> 6)) * HH + (tid & 63)] = hn[tid];

        gx0 = nx0;
        gx1 = nx1;
    }
}

// ---------------------------------------------------------------------------
// Final linear head. grid = T, block = 256.
// ---------------------------------------------------------------------------
__global__ __launch_bounds__(256) void lstm_lin_kernel(
    const float* __restrict__ hseq,   // [T][B][64]
    const float* __restrict__ Wl,     // [64]
    const float* __restrict__ bl,     // [1]
    float* __restrict__ out)          // [B][T]
{
    __shared__ float4 wl4[16];
    const int t = blockIdx.x;
    const int b = threadIdx.x;
    if (threadIdx.x < 16)
        wl4[threadIdx.x] = reinterpret_cast<const float4*>(Wl)[threadIdx.x];
    __syncthreads();

    const float4* hp = reinterpret_cast<const float4*>(hseq + ((size_t)t * BB + b) * HH);
    float acc = bl[0];
#pragma unroll
    for (int k4 = 0; k4 < 16; k4++) {
        const float4 h = hp[k4];
        const float4 w = wl4[k4];
        acc = fmaf(h.x, w.x, acc);
        acc = fmaf(h.y, w.y, acc);
        acc = fmaf(h.z, w.z, acc);
        acc = fmaf(h.w, w.w, acc);
    }
    out[(size_t)b * TT + t] = acc;
}

// ---------------------------------------------------------------------------
extern "C" void kernel_launch(void* const* d_in, const int* in_sizes, int n_in,
                              void* d_out, int out_size)
{
    (void)in_sizes; (void)n_in; (void)out_size;

    const float* x = (const float*)d_in[0];
    const float* Wih[5]; const float* Whh[5]; const float* bih[5]; const float* bhh[5];
    for (int l = 0; l < 5; l++) {
        Wih[l] = (const float*)d_in[1 + 4 * l];
        Whh[l] = (const float*)d_in[2 + 4 * l];
        bih[l] = (const float*)d_in[3 + 4 * l];
        bhh[l] = (const float*)d_in[4 + 4 * l];
    }
    const float* Wl = (const float*)d_in[21];
    const float* bl = (const float*)d_in[22];
    float* out = (float*)d_out;

    float *gx, *hA, *hB;
    cudaGetSymbolAddress((void**)&gx, g_gx);
    cudaGetSymbolAddress((void**)&hA, g_hA);
    cudaGetSymbolAddress((void**)&hB, g_hB);
    float* bufs[2] = { hA, hB };

    // layer 0
    lstm_gx0_kernel<<<TT, 256>>>(x, Wih[0], bih[0], bhh[0], gx);
    lstm_rec_kernel<<<BB / RROWS, 256>>>(gx, Whh[0], bufs[0]);

    // layers 1..4
    for (int l = 1; l < 5; l++) {
        const float* hin = bufs[(l - 1) & 1];
        float* ho = bufs[l & 1];
        lstm_gx_kernel<<<(TT * BB) / 64, 256>>>(hin, Wih[l], bih[l], bhh[l], gx);
        lstm_rec_kernel<<<BB / RROWS, 256>>>(gx, Whh[l], ho);
    }

    // linear head (layer 4 wrote bufs[0])
    lstm_lin_kernel<<<TT, 256>>>(bufs[0], Wl, bl, out);
}